// round 13
// baseline (speedup 1.0000x reference)
#include <cuda_runtime.h>

#define NUM_CLASSES 1000
#define FEAT_DIM 512
#define BATCH 65536
#define NSLAB 32
#define HIST_THREADS 256
#define THREADS 512
#define WARPS_PER_BLOCK (THREADS / 32)      // 16
#define NBLOCKS (BATCH / WARPS_PER_BLOCK)   // 4096

// Per-block partial histograms, transposed: g_part[class][slab].
// Fully overwritten by K1 every call -> no reset, no atomics, deterministic.
__device__ int g_part[NUM_CLASSES * NSLAB];

// K1: 32 blocks; each builds a private smem histogram of its 2048 labels and
// stores it into its slab column with plain STGs. Block 0 zeroes out[0].
// Triggers programmatic launch of K2 immediately: K2's streaming phase is
// independent of the histogram; its epilogue grid-dep-syncs on K1 completion.
__global__ void __launch_bounds__(HIST_THREADS) cl_hist_kernel(
    const long long* __restrict__ labels,
    float* __restrict__ out)
{
    cudaTriggerProgrammaticLaunchCompletion();  // let main start streaming now

    __shared__ int h[NUM_CLASSES];
    for (int c = threadIdx.x; c < NUM_CLASSES; c += HIST_THREADS) h[c] = 0;
    if (blockIdx.x == 0 && threadIdx.x == 0) out[0] = 0.0f;
    __syncthreads();

    const longlong2* lab2 =
        reinterpret_cast<const longlong2*>(labels + (size_t)blockIdx.x * (BATCH / NSLAB));
#pragma unroll
    for (int i = 0; i < 4; i++) {
        longlong2 v = lab2[threadIdx.x * 4 + i];
        atomicAdd(&h[(int)v.x], 1);
        atomicAdd(&h[(int)v.y], 1);
    }
    __syncthreads();

    int b = blockIdx.x;
    for (int c = threadIdx.x; c < NUM_CLASSES; c += HIST_THREADS)
        g_part[c * NSLAB + b] = h[c];
}

// K2: R5's proven main (512 thr, ~32 regs, ~90% occ; streaming feature
// float4s + cached center float4s; count from L1-hot slab line; one
// un-fenced atomicAdd(out) per block). Launched with PDL: the distance
// accumulation runs concurrently with K1; cudaGridDependencySynchronize()
// gates only the count/out epilogue.
__global__ void __launch_bounds__(THREADS) cl_main_kernel(
    const float* __restrict__ features,
    const float* __restrict__ centers,
    const long long* __restrict__ labels,
    float* __restrict__ out)
{
    __shared__ float red[WARPS_PER_BLOCK];

    int warp = threadIdx.x >> 5;
    int lane = threadIdx.x & 31;
    int row = blockIdx.x * WARPS_PER_BLOCK + warp;

    int lab = (int)labels[row];  // warp-uniform broadcast load

    const float4* frow = reinterpret_cast<const float4*>(features + (size_t)row * FEAT_DIM);
    const float4* crow = reinterpret_cast<const float4*>(centers + (size_t)lab * FEAT_DIM);

    float acc = 0.0f;
#pragma unroll
    for (int i = 0; i < 4; i++) {
        float4 a = __ldcs(frow + lane + i * 32);  // evict-first feature stream
        float4 b = __ldg(crow + lane + i * 32);   // cached: centers stay L2-resident
        float dx = a.x - b.x;
        float dy = a.y - b.y;
        float dz = a.z - b.z;
        float dw = a.w - b.w;
        acc += dx * dx + dy * dy + dz * dz + dw * dw;
    }

    // Histogram (and out[0]=0) must be complete before counts are read and
    // before the output atomic.
    cudaGridDependencySynchronize();

    int cnt = __ldg(&g_part[lab * NSLAB + lane]);

#pragma unroll
    for (int o = 16; o; o >>= 1) {
        acc += __shfl_xor_sync(0xffffffffu, acc, o);
        cnt += __shfl_xor_sync(0xffffffffu, cnt, o);
    }

    if (lane == 0) {
        float w = __fdividef(1.0f, (float)cnt * (float)FEAT_DIM) * (1.0f / (float)BATCH);
        red[warp] = acc * w;
    }
    __syncthreads();

    if (warp == 0) {
        float v = (lane < WARPS_PER_BLOCK) ? red[lane] : 0.0f;
#pragma unroll
        for (int o = 8; o; o >>= 1)
            v += __shfl_xor_sync(0xffffffffu, v, o);
        if (lane == 0)
            atomicAdd(out, v);
    }
}

extern "C" void kernel_launch(void* const* d_in, const int* in_sizes, int n_in,
                              void* d_out, int out_size) {
    const float* features = (const float*)d_in[0];
    const float* centers = (const float*)d_in[1];
    const long long* labels = (const long long*)d_in[2];
    float* out = (float*)d_out;

    cl_hist_kernel<<<NSLAB, HIST_THREADS>>>(labels, out);

    // Main with programmatic dependent launch on the same (capture) stream.
    cudaLaunchConfig_t cfg = {};
    cfg.gridDim = dim3(NBLOCKS, 1, 1);
    cfg.blockDim = dim3(THREADS, 1, 1);
    cfg.dynamicSmemBytes = 0;
    cfg.stream = 0;
    cudaLaunchAttribute attrs[1];
    attrs[0].id = cudaLaunchAttributeProgrammaticStreamSerialization;
    attrs[0].val.programmaticStreamSerializationAllowed = 1;
    cfg.attrs = attrs;
    cfg.numAttrs = 1;
    cudaLaunchKernelEx(&cfg, cl_main_kernel, features, centers, labels, out);
}

// round 16
// speedup vs baseline: 1.0702x; 1.0702x over previous
#include <cuda_runtime.h>

#define NUM_CLASSES 1000
#define FEAT_DIM 512
#define BATCH 65536
#define NSLAB 32
#define THREADS 512
#define WARPS_PER_BLOCK (THREADS / 32)      // 16
#define NBLOCKS (BATCH / WARPS_PER_BLOCK)   // 4096

// Scratch. g_part fully overwritten each call (same values every call, since
// inputs are fixed). g_done/g_exit/g_accum are zero at module load and reset
// by the last-exiting block each call.
__device__ int g_part[NUM_CLASSES * NSLAB];
__device__ unsigned int g_done;
__device__ unsigned int g_exit;
__device__ float g_accum;

__device__ __forceinline__ unsigned int ld_acquire(const unsigned int* p) {
    unsigned int v;
    asm volatile("ld.global.acquire.gpu.b32 %0, [%1];" : "=r"(v) : "l"(p) : "memory");
    return v;
}
__device__ __forceinline__ void red_add_release(unsigned int* p, unsigned int v) {
    asm volatile("red.global.add.release.gpu.u32 [%0], %1;" :: "l"(p), "r"(v) : "memory");
}
__device__ __forceinline__ unsigned int atom_add_acqrel(unsigned int* p, unsigned int v) {
    unsigned int o;
    asm volatile("atom.global.add.acq_rel.gpu.u32 %0, [%1], %2;"
                 : "=r"(o) : "l"(p), "r"(v) : "memory");
    return o;
}
__device__ __forceinline__ float ldcg_f(const float* p) {
    float v;
    asm volatile("ld.global.cg.f32 %0, [%1];" : "=f"(v) : "l"(p) : "memory");
    return v;
}
// COHERENT read of same-kernel-produced data: must bypass L1/RO path.
__device__ __forceinline__ int ldcg_i(const int* p) {
    int v;
    asm volatile("ld.global.cg.s32 %0, [%1];" : "=r"(v) : "l"(p) : "memory");
    return v;
}

// Single fused kernel. Blocks 0..31 additionally build the label histogram
// (hidden under the feature stream of the other 4064 blocks). Streaming body
// is byte-equivalent to the proven 25.1us R5 kernel. Epilogue accumulates
// into g_accum; last-exit block writes out[0] and resets scratch.
__global__ void __launch_bounds__(THREADS, 4) cl_fused_kernel(
    const float* __restrict__ features,
    const float* __restrict__ centers,
    const long long* __restrict__ labels,
    float* __restrict__ out)
{
    __shared__ int h[NUM_CLASSES];
    __shared__ float red[WARPS_PER_BLOCK];

    int tid = threadIdx.x;
    int warp = tid >> 5;
    int lane = tid & 31;
    int bid = blockIdx.x;

    // ---- inline histogram duty (blocks 0..31 only) ----
    if (bid < NSLAB) {
        for (int c = tid; c < NUM_CLASSES; c += THREADS) h[c] = 0;
        __syncthreads();
        const longlong2* lab2 =
            reinterpret_cast<const longlong2*>(labels + (size_t)bid * (BATCH / NSLAB));
#pragma unroll
        for (int i = 0; i < 2; i++) {
            longlong2 v = lab2[tid * 2 + i];
            atomicAdd(&h[(int)v.x], 1);
            atomicAdd(&h[(int)v.y], 1);
        }
        __syncthreads();
        for (int c = tid; c < NUM_CLASSES; c += THREADS)
            g_part[c * NSLAB + bid] = h[c];
        __syncthreads();
        if (tid == 0)
            red_add_release(&g_done, 1u);  // publish (release orders the STGs)
    }

    // ---- streaming body (identical to R5's proven 25.1us loop) ----
    int row = bid * WARPS_PER_BLOCK + warp;
    int lab = (int)labels[row];  // warp-uniform broadcast load

    const float4* frow = reinterpret_cast<const float4*>(features + (size_t)row * FEAT_DIM);
    const float4* crow = reinterpret_cast<const float4*>(centers + (size_t)lab * FEAT_DIM);

    float acc = 0.0f;
#pragma unroll
    for (int i = 0; i < 4; i++) {
        float4 a = __ldcs(frow + lane + i * 32);  // evict-first feature stream
        float4 b = __ldg(crow + lane + i * 32);   // cached: centers stay L2-resident
        float dx = a.x - b.x;
        float dy = a.y - b.y;
        float dz = a.z - b.z;
        float dw = a.w - b.w;
        acc += dx * dx + dy * dy + dz * dz + dw * dw;
    }

    // ---- wait for histogram publication (t0 polls w/ backoff, bar spreads) ----
    if (tid == 0) {
        while (ld_acquire(&g_done) < NSLAB)
            __nanosleep(64);
    }
    __syncthreads();

    // COHERENT count read (written this kernel on other SMs): ld.cg, NOT __ldg.
    int cnt = ldcg_i(&g_part[lab * NSLAB + lane]);

#pragma unroll
    for (int o = 16; o; o >>= 1) {
        acc += __shfl_xor_sync(0xffffffffu, acc, o);
        cnt += __shfl_xor_sync(0xffffffffu, cnt, o);
    }

    if (lane == 0) {
        float w = __fdividef(1.0f, (float)cnt * (float)FEAT_DIM) * (1.0f / (float)BATCH);
        red[warp] = acc * w;
    }
    __syncthreads();

    if (warp == 0) {
        float v = (lane < WARPS_PER_BLOCK) ? red[lane] : 0.0f;
#pragma unroll
        for (int o = 8; o; o >>= 1)
            v += __shfl_xor_sync(0xffffffffu, v, o);
        if (lane == 0) {
            atomicAdd(&g_accum, v);
            // acq_rel ticket: release orders our accum-add before the tick;
            // acquire lets the last block read the completed total.
            unsigned int t = atom_add_acqrel(&g_exit, 1u);
            if (t == NBLOCKS - 1) {
                out[0] = ldcg_f(&g_accum);
                // reset scratch for the next graph replay
                g_accum = 0.0f;
                g_exit = 0u;
                g_done = 0u;
            }
        }
    }
}

extern "C" void kernel_launch(void* const* d_in, const int* in_sizes, int n_in,
                              void* d_out, int out_size) {
    const float* features = (const float*)d_in[0];
    const float* centers = (const float*)d_in[1];
    const long long* labels = (const long long*)d_in[2];
    float* out = (float*)d_out;

    cl_fused_kernel<<<NBLOCKS, THREADS>>>(features, centers, labels, out);
}